// round 4
// baseline (speedup 1.0000x reference)
#include <cuda_runtime.h>
#include <math.h>

#ifndef M_PI
#define M_PI 3.14159265358979323846
#endif

#define N_TOT   8388608
#define W       882
#define WP      884           // padded row stride (16B-aligned rows)
#define NB      9510          // N_TOT / W
#define REM     788           // N_TOT - NB*W
#define MCH     64            // karplus steps per chunk
#define NFULL   148           // full chunks
#define NCH     149           // total chunks (last has 38 steps)
#define LASTS   38
#define GLEN    19            // karplus chunks per group
#define NG      8             // groups (7*19=133, last group 16 chunks)
#define AOFF    768           // f[] circular-extension offset
#define FSZ     1660          // f[] size: W + AOFF + 10
#define LBQ     256           // biquad chunk length
#define PBQ     32768         // biquad chunk count (LBQ*PBQ = N_TOT)
#define CPT     32            // biquad chunks per scan thread
#define SRATE   44100.0

// ---- scratch (device globals; no allocation allowed) ----
__device__ float  g_wt[W];                 // filtered wavetable
__device__ float  g_dstate[NCH * WP];      // karplus chunk end-states (zero-init runs)
__device__ float  g_vstart[NCH * WP];      // karplus chunk start-states
__device__ float  g_gend[NG * WP];         // zero-init group end states (g=1..6)
__device__ float  g_gx[NG * WP];           // true group start states X_g (g=1..7)
__device__ float  g_ks[N_TOT];             // karplus output = band-reject input
__device__ float  g_bqd[PBQ * 2];          // biquad per-chunk zero-init end states
__device__ float  g_bqs[PBQ * 2];          // biquad per-chunk start states
__device__ double g_Ms[16][4];             // M^(LBQ * 2^s), s = 0..15
__device__ float  g_par[12];               // 0:d2 1:fa 2..6:bq 7:ia 8:ir 9:sg
__device__ float  g_Kt[GLEN * 256];        // reversed taps of S^(64k), k=1..19
__device__ int    g_Kwk[GLEN + 1];         // tap count (mult of 4)
__device__ int    g_Koff[GLEN + 1];        // f-index offset (mult of 4)

// geometry of truncated kernel for S^(64k)
__device__ __forceinline__ void kgeom(int k, int& c0, int& wk) {
    int m = 64 * k;
    int hw = (int)ceil(23.0 * sqrt((double)k));
    c0 = m / 2 - hw;
    wk = (2 * hw + 3) & ~3;
    c0 -= (c0 + wk - 1) & 3;      // force (c0+wk) % 4 == 1
}

// ============================================================
// Setup (1 block x 1024): K-table (parallel), scalars (t0)
// ============================================================
__global__ void __launch_bounds__(1024) setup_kernel(const float* __restrict__ wavetable,
                             const float* __restrict__ h,
                             const float* __restrict__ envp,
                             const float* __restrict__ lp2) {
    int tid = threadIdx.x;

    double decay = (double)h[0] / 10.0 + 0.9;
    decay = fmin(fmax(decay, 0.9), 0.999);
    double d2 = decay * 0.5;
    double ld2 = log(d2);

    // ---- K table: reversed truncated taps of S^(64k) ----
    for (int idx = tid; idx < GLEN * 256; idx += 1024) {
        int k = idx / 256 + 1;
        int jj = idx % 256;
        int c0, wk; kgeom(k, c0, wk);
        int m = 64 * k;
        float val = 0.0f;
        if (jj < wk) {
            int j = c0 + wk - 1 - jj;
            if (j >= 0 && j <= m) {
                double lg = lgamma((double)(m + 1)) - lgamma((double)(j + 1))
                          - lgamma((double)(m - j + 1)) + (double)m * ld2;
                val = (float)exp(lg);
            }
        }
        g_Kt[idx] = val;
    }
    if (tid >= 1 && tid <= GLEN) {
        int c0, wk; kgeom(tid, c0, wk);
        g_Kwk[tid] = wk;
        g_Koff[tid] = AOFF + 1 - c0 - wk;
    }

    if (tid != 0) return;

    double h1 = h[1], h2 = h[2], h3 = h[3], h4 = h[4], h5 = h[5], h6 = h[6];

    // ---- lowpass 1 coefs ----
    double lpf = h1 * SRATE / 4.0; lpf = fmin(fmax(lpf, 100.0), SRATE / 2.0 - 1.0);
    double lpq = fmin(fmax(h2, 0.1), 0.999);
    double w0 = 2.0 * M_PI * lpf / SRATE, al = sin(w0) / (2.0 * lpq), cw = cos(w0);
    double a0 = 1.0 + al;
    float f1b0 = (float)(((1.0 - cw) * 0.5) / a0), f1b1 = (float)((1.0 - cw) / a0);
    float f1b2 = f1b0;
    float f1a1 = (float)((-2.0 * cw) / a0), f1a2 = (float)((1.0 - al) / a0);

    // ---- lowpass 2 coefs ----
    double c2 = 100.0 + (double)lp2[0] * 8000.0;
    double w02 = 2.0 * M_PI * c2 / SRATE, al2 = sin(w02) / (2.0 * 0.707), cw2 = cos(w02);
    double a02 = 1.0 + al2;
    float f2b0 = (float)(((1.0 - cw2) * 0.5) / a02), f2b1 = (float)((1.0 - cw2) / a02);
    float f2b2 = f2b0;
    float f2a1 = (float)((-2.0 * cw2) / a02), f2a2 = (float)((1.0 - al2) / a02);

    // ---- cascade over wavetable (882 samples, serial f32) ----
    {
        float x1 = 0.f, x2 = 0.f, y1 = 0.f, y2 = 0.f, u1 = 0.f, u2 = 0.f, v1 = 0.f, v2 = 0.f;
        for (int i = 0; i < W; i++) {
            float xn = wavetable[i];
            float yn = f1b0 * xn + f1b1 * x1 + f1b2 * x2 - f1a1 * y1 - f1a2 * y2;
            x2 = x1; x1 = xn; y2 = y1; y1 = yn;
            float zn = f2b0 * yn + f2b1 * u1 + f2b2 * u2 - f2a1 * v1 - f2a2 * v2;
            u2 = u1; u1 = yn; v2 = v1; v1 = zn;
            g_wt[i] = zn;
        }
    }

    // ---- band-reject coefs ----
    double brf = h5 * SRATE / 4.0; brf = fmin(fmax(brf, 100.0), SRATE / 2.0 - 1.0);
    double brq = fmin(fmax(h6, 0.1), 0.999);
    double w0b = 2.0 * M_PI * brf / SRATE, alb = sin(w0b) / (2.0 * brq), cwb = cos(w0b);
    double a0b = 1.0 + alb;
    double bb0 = 1.0 / a0b, bb1 = (-2.0 * cwb) / a0b, bb2 = 1.0 / a0b;
    double ba1 = (-2.0 * cwb) / a0b, ba2 = (1.0 - alb) / a0b;

    // ---- M^(LBQ * 2^s), s=0..15 by repeated squaring ----
    {
        double m00 = -ba1, m01 = -ba2, m10 = 1.0, m11 = 0.0;   // M
        for (int s = 0; s < 8; s++) {                           // -> M^256
            double n00 = m00 * m00 + m01 * m10, n01 = m00 * m01 + m01 * m11;
            double n10 = m10 * m00 + m11 * m10, n11 = m10 * m01 + m11 * m11;
            m00 = n00; m01 = n01; m10 = n10; m11 = n11;
        }
        for (int s = 0; s < 16; s++) {
            g_Ms[s][0] = m00; g_Ms[s][1] = m01; g_Ms[s][2] = m10; g_Ms[s][3] = m11;
            double n00 = m00 * m00 + m01 * m10, n01 = m00 * m01 + m01 * m11;
            double n10 = m10 * m00 + m11 * m10, n11 = m10 * m01 + m11 * m11;
            m00 = n00; m01 = n01; m10 = n10; m11 = n11;
        }
    }

    // ---- envelope ----
    double nD = (double)N_TOT;
    double attack  = 1.0 + (double)envp[0] * 0.1 * nD;
    double release = 1.0 + (double)envp[2] * 0.1 * nD;
    double sustain = fmin(fmax((double)envp[1], 0.0), 1.0);

    g_par[0] = (float)d2;
    g_par[1] = (float)h3;
    g_par[2] = (float)bb0; g_par[3] = (float)bb1; g_par[4] = (float)bb2;
    g_par[5] = (float)ba1; g_par[6] = (float)ba2;
    g_par[7] = (float)(1.0 / attack);
    g_par[8] = (float)(1.0 / release);
    g_par[9] = (float)(sustain * h4);
}

// ============================================================
// Circular-conv helpers. f[t] = v[(t - AOFF) mod W], t in [0,FSZ)
// ============================================================
__device__ __forceinline__ void f_write(float* f, int p, float v) {
    f[p + AOFF] = v;
    if (p >= W - AOFF) f[p - (W - AOFF)] = v;      // W-AOFF = 114
    if (p < FSZ - (W + AOFF)) f[p + W + AOFF] = v; // p < 10
}

// acc_e += sum_j K[j] * v[(o0+e - j) mod W], taps reversed in Ks
__device__ __forceinline__ void conv_into(const float* __restrict__ f,
                                          const float* __restrict__ Ks,
                                          int wk, int off, int o0, float* acc) {
    int b0 = o0 + off;
    float4 da = *(const float4*)&f[b0];
    #pragma unroll 2
    for (int jj = 0; jj < wk; jj += 4) {
        float4 ka = *(const float4*)&Ks[jj];
        float4 db = *(const float4*)&f[b0 + jj + 4];
        acc[0] = fmaf(ka.x, da.x, acc[0]); acc[0] = fmaf(ka.y, da.y, acc[0]);
        acc[0] = fmaf(ka.z, da.z, acc[0]); acc[0] = fmaf(ka.w, da.w, acc[0]);
        acc[1] = fmaf(ka.x, da.y, acc[1]); acc[1] = fmaf(ka.y, da.z, acc[1]);
        acc[1] = fmaf(ka.z, da.w, acc[1]); acc[1] = fmaf(ka.w, db.x, acc[1]);
        acc[2] = fmaf(ka.x, da.z, acc[2]); acc[2] = fmaf(ka.y, da.w, acc[2]);
        acc[2] = fmaf(ka.z, db.x, acc[2]); acc[2] = fmaf(ka.w, db.y, acc[2]);
        acc[3] = fmaf(ka.x, da.w, acc[3]); acc[3] = fmaf(ka.y, db.x, acc[3]);
        acc[3] = fmaf(ka.z, db.y, acc[3]); acc[3] = fmaf(ka.w, db.z, acc[3]);
        da = db;
    }
}

// ============================================================
// Karplus chunk runner: 1 barrier per step, prefetch depth 4
// ============================================================
template<int NS, bool WRITE>
__device__ __forceinline__ void ks_run(const float* __restrict__ fp,
                                       float* __restrict__ op,
                                       float& a, float (*b)[W],
                                       bool act, int i, int im1,
                                       float d2, float fa) {
    float xr[4];
    #pragma unroll
    for (int q = 0; q < 4; q++)
        xr[q] = (act && q < NS) ? fp[(size_t)q * W] : 0.0f;

    #pragma unroll 4
    for (int s = 0; s < NS; s++) {
        float x = xr[s & 3];
        if (act && (s + 4) < NS) xr[s & 3] = fp[(size_t)(s + 4) * W];
        float u = tanhf(fa * x);
        float t = a + u;
        if (act) b[s & 1][i] = t;
        __syncthreads();
        if (act) {
            a = d2 * (t + b[s & 1][im1]);
            if (WRITE) op[(size_t)s * W] = a;
        }
        // no trailing barrier: next iter writes the OTHER buffer;
        // its own barrier orders the reads.
    }
}

// ============================================================
// Karplus pass 1: zero-init chunk runs -> end states d_c
// ============================================================
__global__ void __launch_bounds__(896) ks_pass1(const float* __restrict__ fb) {
    __shared__ float b[2][W];
    int c = blockIdx.x;
    int i = threadIdx.x;
    bool act = i < W;
    int im1 = (i == 0) ? (W - 1) : (i - 1);
    float d2 = g_par[0], fa = g_par[1];

    float a = 0.0f;
    const float* fp = fb + (size_t)c * MCH * W + i;
    ks_run<MCH, false>(fp, nullptr, a, b, act, i, im1, d2, fa);
    if (act) g_dstate[c * WP + i] = a;
}

// ============================================================
// Combine phase A: 8 groups in parallel; sequential 48-tap convs
// within each group (group 0 from wt = true; others zero-init).
// ============================================================
__global__ void __launch_bounds__(256) comb_A() {
    __shared__ __align__(16) float f[FSZ];
    __shared__ __align__(16) float Ks[256];
    int g = blockIdx.x, t = threadIdx.x;
    Ks[t] = g_Kt[t];                       // k=1 row
    int wk = g_Kwk[1], off = g_Koff[1];
    int c1 = g * GLEN;
    int len = (g == NG - 1) ? (NCH - (NG - 1) * GLEN) : GLEN;   // 16 or 19
    int cend  = c1 + len;
    int cendT = (g == NG - 1) ? (NCH - 1) : cend;

    int cbeg;
    if (g == 0) {
        for (int p = t; p < W; p += 256) {
            float v = g_wt[p];
            f_write(f, p, v);
            g_vstart[p] = v;
        }
        cbeg = 1;
    } else {
        for (int p = t; p < W; p += 256) {
            float v = g_dstate[c1 * WP + p];
            f_write(f, p, v);
            g_vstart[(c1 + 1) * WP + p] = v;
        }
        cbeg = c1 + 2;
    }
    __syncthreads();

    int o0 = t * 4;
    bool activ = o0 < W;
    for (int c = cbeg; c <= cendT; c++) {
        float acc[4] = {0.f, 0.f, 0.f, 0.f};
        if (activ) {
            const float* dp = g_dstate + (size_t)(c - 1) * WP + o0;
            acc[0] = dp[0]; acc[1] = dp[1]; acc[2] = dp[2]; acc[3] = dp[3];
            conv_into(f, Ks, wk, off, o0, acc);
        }
        __syncthreads();
        if (activ) {
            float* dst;
            if (c < cend) dst = g_vstart + (size_t)c * WP + o0;
            else if (g == 0) dst = g_gx + WP + o0;        // X_1
            else dst = g_gend + (size_t)g * WP + o0;      // Z_g
            #pragma unroll
            for (int e = 0; e < 4; e++) {
                int p = o0 + e;
                if (p < W) { f_write(f, p, acc[e]); dst[e] = acc[e]; }
            }
        }
        __syncthreads();
    }
}

// ============================================================
// Combine phase B: 1 block; X_{g+1} = K19 (*) X_g + Z_g, g=1..6
// ============================================================
__global__ void __launch_bounds__(256) comb_B() {
    __shared__ __align__(16) float f[FSZ];
    __shared__ __align__(16) float Ks[256];
    int t = threadIdx.x;
    Ks[t] = g_Kt[(GLEN - 1) * 256 + t];    // k=19 row
    int wk = g_Kwk[GLEN], off = g_Koff[GLEN];

    for (int p = t; p < W; p += 256) f_write(f, p, g_gx[WP + p]);   // X_1
    __syncthreads();

    int o0 = t * 4;
    bool activ = o0 < W;
    for (int g = 1; g <= NG - 2; g++) {
        float acc[4] = {0.f, 0.f, 0.f, 0.f};
        if (activ) {
            const float* zp = g_gend + (size_t)g * WP + o0;
            acc[0] = zp[0]; acc[1] = zp[1]; acc[2] = zp[2]; acc[3] = zp[3];
            conv_into(f, Ks, wk, off, o0, acc);
        }
        __syncthreads();
        if (activ) {
            float* dst = g_gx + (size_t)(g + 1) * WP + o0;
            #pragma unroll
            for (int e = 0; e < 4; e++) {
                int p = o0 + e;
                if (p < W) { f_write(f, p, acc[e]); dst[e] = acc[e]; }
            }
        }
        __syncthreads();
    }
}

// ============================================================
// Combine phase C: chunks 19..148 in parallel:
// vstart[c] (true) = vstart[c] (zero-init) + K_r (*) X_g,  r=c-19g
// ============================================================
__global__ void __launch_bounds__(256) comb_C() {
    __shared__ __align__(16) float f[FSZ];
    __shared__ __align__(16) float Ks[256];
    int t = threadIdx.x;
    int c = GLEN + blockIdx.x;             // 19..148
    int g = c / GLEN, r = c - g * GLEN;

    if (r == 0) {                          // true start = X_g
        for (int p = t; p < W; p += 256)
            g_vstart[(size_t)c * WP + p] = g_gx[(size_t)g * WP + p];
        return;
    }

    Ks[t] = g_Kt[(r - 1) * 256 + t];
    int wk = g_Kwk[r], off = g_Koff[r];
    for (int p = t; p < W; p += 256) f_write(f, p, g_gx[(size_t)g * WP + p]);
    __syncthreads();

    int o0 = t * 4;
    if (o0 < W) {
        float* vp = g_vstart + (size_t)c * WP + o0;
        float acc[4] = {vp[0], vp[1], vp[2], vp[3]};
        conv_into(f, Ks, wk, off, o0, acc);
        #pragma unroll
        for (int e = 0; e < 4; e++)
            if (o0 + e < W) vp[e] = acc[e];
    }
}

// ============================================================
// Karplus pass 2: replay chunks from exact start states
// ============================================================
__global__ void __launch_bounds__(896) ks_pass2(const float* __restrict__ fb) {
    __shared__ float b[2][W];
    int c = blockIdx.x;
    int i = threadIdx.x;
    bool act = i < W;
    int im1 = (i == 0) ? (W - 1) : (i - 1);
    float d2 = g_par[0], fa = g_par[1];

    float a = act ? g_vstart[(size_t)c * WP + i] : 0.0f;
    __syncthreads();

    const float* fp = fb   + (size_t)c * MCH * W + i;
    float*       op = g_ks + (size_t)c * MCH * W + i;

    if (c < NCH - 1) {
        ks_run<MCH, true>(fp, op, a, b, act, i, im1, d2, fa);
    } else {
        ks_run<LASTS, true>(fp, op, a, b, act, i, im1, d2, fa);
        __syncthreads();
        if (act) b[0][i] = a;
        __syncthreads();
        if (i < REM) {
            float fin = d2 * (b[0][i] + b[0][im1]);
            int g = NB * W + i;
            if (g >= N_TOT - 256) fin *= (float)(N_TOT - 1 - g) * (1.0f / 255.0f);
            g_ks[g] = fin;
        }
    }
}

// ============================================================
// Band-reject pass A: per-chunk zero-init runs, prefetch ring 8
// ============================================================
__global__ void __launch_bounds__(256) bq_passA() {
    int c = blockIdx.x * 256 + threadIdx.x;
    float b0 = g_par[2], b1 = g_par[3], b2 = g_par[4], a1 = g_par[5], a2 = g_par[6];
    size_t start = (size_t)c * LBQ;
    float x1 = (c > 0) ? g_ks[start - 1] : 0.0f;
    float x2 = (c > 0) ? g_ks[start - 2] : 0.0f;
    float y1 = 0.0f, y2 = 0.0f;
    const float4* kp = (const float4*)(g_ks + start);
    float4 buf[8];
    #pragma unroll
    for (int q = 0; q < 8; q++) buf[q] = kp[q];
    #pragma unroll 8
    for (int q = 0; q < LBQ / 4; q++) {
        float4 v = buf[q & 7];
        if (q + 8 < LBQ / 4) buf[q & 7] = kp[q + 8];
        float xs[4] = {v.x, v.y, v.z, v.w};
        #pragma unroll
        for (int e = 0; e < 4; e++) {
            float xn = xs[e];
            float cn = b0 * xn + b1 * x1 + b2 * x2;
            float yn = cn - a1 * y1 - a2 * y2;
            x2 = x1; x1 = xn; y2 = y1; y1 = yn;
        }
    }
    g_bqd[2 * c] = y1;
    g_bqd[2 * c + 1] = y2;
}

// ============================================================
// Band-reject scan: 1024 threads x 32 chunks pre-combine,
// Kogge-Stone over 1024 aggregates, replay start states.
// ============================================================
__global__ void __launch_bounds__(1024) bq_scan() {
    __shared__ float2 sv[1024];
    int t = threadIdx.x;
    float A00 = (float)g_Ms[0][0], A01 = (float)g_Ms[0][1];
    float A10 = (float)g_Ms[0][2], A11 = (float)g_Ms[0][3];

    float4 db[CPT / 2];
    #pragma unroll
    for (int i = 0; i < CPT / 2; i++)
        db[i] = ((const float4*)g_bqd)[t * (CPT / 2) + i];

    float vx = 0.f, vy = 0.f;
    #pragma unroll
    for (int i = 0; i < CPT / 2; i++) {
        float nx = A00 * vx + A01 * vy + db[i].x;
        float ny = A10 * vx + A11 * vy + db[i].y;
        vx = nx; vy = ny;
        nx = A00 * vx + A01 * vy + db[i].z;
        ny = A10 * vx + A11 * vy + db[i].w;
        vx = nx; vy = ny;
    }
    sv[t] = make_float2(vx, vy);
    __syncthreads();

    for (int s = 0; s < 10; s++) {
        int offs = 1 << s;
        float B00 = (float)g_Ms[5 + s][0], B01 = (float)g_Ms[5 + s][1];
        float B10 = (float)g_Ms[5 + s][2], B11 = (float)g_Ms[5 + s][3];
        float ax = 0.f, ay = 0.f;
        if (t >= offs) {
            float2 src = sv[t - offs];
            ax = B00 * src.x + B01 * src.y;
            ay = B10 * src.x + B11 * src.y;
        }
        __syncthreads();
        sv[t].x += ax; sv[t].y += ay;
        __syncthreads();
    }

    float px = 0.f, py = 0.f;
    if (t > 0) { px = sv[t - 1].x; py = sv[t - 1].y; }
    float4 outp[CPT / 2];
    #pragma unroll
    for (int i = 0; i < CPT / 2; i++) {
        outp[i].x = px; outp[i].y = py;
        float nx = A00 * px + A01 * py + db[i].x;
        float ny = A10 * px + A11 * py + db[i].y;
        px = nx; py = ny;
        outp[i].z = px; outp[i].w = py;
        nx = A00 * px + A01 * py + db[i].z;
        ny = A10 * px + A11 * py + db[i].w;
        px = nx; py = ny;
    }
    #pragma unroll
    for (int i = 0; i < CPT / 2; i++)
        ((float4*)g_bqs)[t * (CPT / 2) + i] = outp[i];
}

// ============================================================
// Band-reject pass B: replay + fused envelope
// ============================================================
__global__ void __launch_bounds__(256) bq_passB(float* __restrict__ out) {
    int c = blockIdx.x * 256 + threadIdx.x;
    float b0 = g_par[2], b1 = g_par[3], b2 = g_par[4], a1 = g_par[5], a2 = g_par[6];
    float ia = g_par[7], ir = g_par[8], sg = g_par[9];
    size_t start = (size_t)c * LBQ;
    float x1 = (c > 0) ? g_ks[start - 1] : 0.0f;
    float x2 = (c > 0) ? g_ks[start - 2] : 0.0f;
    float y1 = g_bqs[2 * c], y2 = g_bqs[2 * c + 1];
    const float4* kp = (const float4*)(g_ks + start);
    float4*       op = (float4*)(out + start);
    float4 buf[8];
    #pragma unroll
    for (int q = 0; q < 8; q++) buf[q] = kp[q];
    #pragma unroll 8
    for (int q = 0; q < LBQ / 4; q++) {
        float4 v = buf[q & 7];
        if (q + 8 < LBQ / 4) buf[q & 7] = kp[q + 8];
        float xs[4] = {v.x, v.y, v.z, v.w};
        float ys[4];
        int n0 = (int)start + q * 4;
        #pragma unroll
        for (int e = 0; e < 4; e++) {
            float xn = xs[e];
            float cn = b0 * xn + b1 * x1 + b2 * x2;
            float yn = cn - a1 * y1 - a2 * y2;
            x2 = x1; x1 = xn; y2 = y1; y1 = yn;
            float fn = (float)(n0 + e);
            float e1 = fminf(fn * ia, 1.0f);
            float e2 = fminf(((float)(N_TOT - 1) - fn) * ir, 1.0f);
            ys[e] = yn * e1 * e2 * sg;
        }
        op[q] = make_float4(ys[0], ys[1], ys[2], ys[3]);
    }
}

// ============================================================
extern "C" void kernel_launch(void* const* d_in, const int* in_sizes, int n_in,
                              void* d_out, int out_size) {
    const float* fb  = (const float*)d_in[0];
    const float* wt  = (const float*)d_in[1];
    const float* h   = (const float*)d_in[2];
    const float* ep  = (const float*)d_in[3];
    const float* lp2 = (const float*)d_in[4];
    float* out = (float*)d_out;

    setup_kernel<<<1, 1024>>>(wt, h, ep, lp2);
    ks_pass1<<<NCH - 1, 896>>>(fb);          // zero-init ends for chunks 0..147
    comb_A<<<NG, 256>>>();
    comb_B<<<1, 256>>>();
    comb_C<<<NCH - GLEN, 256>>>();
    ks_pass2<<<NCH, 896>>>(fb);
    bq_passA<<<PBQ / 256, 256>>>();
    bq_scan<<<1, 1024>>>();
    bq_passB<<<PBQ / 256, 256>>>(out);
}

// round 5
// speedup vs baseline: 2.2347x; 2.2347x over previous
#include <cuda_runtime.h>
#include <math.h>

#ifndef M_PI
#define M_PI 3.14159265358979323846
#endif

#define N_TOT   8388608
#define W       882
#define WP      884           // padded row stride (16B-aligned rows)
#define NB      9510          // N_TOT / W
#define REM     788           // N_TOT - NB*W
#define MCH     64            // karplus steps per chunk
#define NCH     149           // total chunks (last has 38 steps)
#define LASTS   38
#define GLEN    19            // karplus chunks per group
#define NG      8             // groups
#define AOFF    768           // f[] circular-extension offset
#define FSZ     1660          // f[] size
#define LBQ     512           // biquad chunk length
#define PBQ     16384         // biquad chunk count
#define CPT     32            // biquad chunks per scan thread
#define SRATE   44100.0

// ---- scratch (device globals; no allocation allowed) ----
__device__ float  g_wt[W];
__device__ float  g_dstate[NCH * WP];
__device__ float  g_vstart[NCH * WP];
__device__ float  g_gend[NG * WP];
__device__ float  g_gx[NG * WP];
__device__ float  g_ks[N_TOT];
__device__ float  g_bqd[PBQ * 2];
__device__ float  g_bqs[PBQ * 2];
__device__ double g_Ms[16][4];             // M^(LBQ * 2^s), s = 0..15
__device__ float  g_par[12];               // 0:d2 1:fa2(=2*fa) 2..6:bq 7:ia 8:ir 9:sg
__device__ float  g_Kt[GLEN * 256];        // reversed taps of S^(64k), k=1..19
__device__ int    g_Kwk[GLEN + 1];
__device__ int    g_Koff[GLEN + 1];

// geometry of truncated kernel for S^(64k) (~5.25 sigma)
__device__ __forceinline__ void kgeom(int k, int& c0, int& wk) {
    int m = 64 * k;
    int hw = (int)ceil(21.0 * sqrt((double)k));
    c0 = m / 2 - hw;
    wk = (2 * hw + 4) & ~3;
    c0 -= (c0 + wk - 1) & 3;      // force (c0+wk) % 4 == 1
}

// fast tanh: (e-1)/(e+1), e=exp(2x); |2x| <= ~1.4 here, no overflow
__device__ __forceinline__ float ftanh2(float x2) {   // x2 = 2*x
    float e = __expf(x2);
    return __fdividef(e - 1.0f, e + 1.0f);
}

// ============================================================
// Scalars only (1 warp): bq coefs, M powers, envelope, kgeom LUT
// ============================================================
__global__ void setup_scalars(const float* __restrict__ h,
                              const float* __restrict__ envp) {
    int tid = threadIdx.x;
    if (tid >= 1 && tid <= GLEN) {
        int c0, wk; kgeom(tid, c0, wk);
        g_Kwk[tid] = wk;
        g_Koff[tid] = AOFF + 1 - c0 - wk;
    }
    if (tid != 0) return;

    double decay = (double)h[0] / 10.0 + 0.9;
    decay = fmin(fmax(decay, 0.9), 0.999);

    double h5 = h[5], h6 = h[6];
    double brf = h5 * SRATE / 4.0; brf = fmin(fmax(brf, 100.0), SRATE / 2.0 - 1.0);
    double brq = fmin(fmax(h6, 0.1), 0.999);
    double w0b = 2.0 * M_PI * brf / SRATE, alb = sin(w0b) / (2.0 * brq), cwb = cos(w0b);
    double a0b = 1.0 + alb;
    double bb0 = 1.0 / a0b, bb1 = (-2.0 * cwb) / a0b, bb2 = 1.0 / a0b;
    double ba1 = (-2.0 * cwb) / a0b, ba2 = (1.0 - alb) / a0b;

    // M^(LBQ * 2^s), LBQ=512
    {
        double m00 = -ba1, m01 = -ba2, m10 = 1.0, m11 = 0.0;
        for (int s = 0; s < 9; s++) {                   // -> M^512
            double n00 = m00 * m00 + m01 * m10, n01 = m00 * m01 + m01 * m11;
            double n10 = m10 * m00 + m11 * m10, n11 = m10 * m01 + m11 * m11;
            m00 = n00; m01 = n01; m10 = n10; m11 = n11;
        }
        for (int s = 0; s < 16; s++) {
            g_Ms[s][0] = m00; g_Ms[s][1] = m01; g_Ms[s][2] = m10; g_Ms[s][3] = m11;
            double n00 = m00 * m00 + m01 * m10, n01 = m00 * m01 + m01 * m11;
            double n10 = m10 * m00 + m11 * m10, n11 = m10 * m01 + m11 * m11;
            m00 = n00; m01 = n01; m10 = n10; m11 = n11;
        }
    }

    double nD = (double)N_TOT;
    double attack  = 1.0 + (double)envp[0] * 0.1 * nD;
    double release = 1.0 + (double)envp[2] * 0.1 * nD;
    double sustain = fmin(fmax((double)envp[1], 0.0), 1.0);

    g_par[0] = (float)(decay * 0.5);
    g_par[1] = (float)(2.0 * (double)h[3]);     // 2*feedbackamt for ftanh2
    g_par[2] = (float)bb0; g_par[3] = (float)bb1; g_par[4] = (float)bb2;
    g_par[5] = (float)ba1; g_par[6] = (float)ba2;
    g_par[7] = (float)(1.0 / attack);
    g_par[8] = (float)(1.0 / release);
    g_par[9] = (float)(sustain * (double)h[4]);
}

// ============================================================
// K-table: chip-parallel, 1 tap per thread (DP lgamma spread out)
// ============================================================
__global__ void ktab_kernel(const float* __restrict__ h) {
    int idx = blockIdx.x * 32 + threadIdx.x;
    if (idx >= GLEN * 256) return;
    double decay = (double)h[0] / 10.0 + 0.9;
    decay = fmin(fmax(decay, 0.9), 0.999);
    double ld2 = log(decay * 0.5);

    int k = idx / 256 + 1;
    int jj = idx % 256;
    int c0, wk; kgeom(k, c0, wk);
    int m = 64 * k;
    float val = 0.0f;
    if (jj < wk) {
        int j = c0 + wk - 1 - jj;
        if (j >= 0 && j <= m) {
            double lg = lgamma((double)(m + 1)) - lgamma((double)(j + 1))
                      - lgamma((double)(m - j + 1)) + (double)m * ld2;
            val = (float)exp(lg);
        }
    }
    g_Kt[idx] = val;
}

// ============================================================
// Wavetable prefilter: two cascaded biquads, each a blocked
// affine scan over (y1,y2): 128 threads x 7 samples.
// ============================================================
__global__ void __launch_bounds__(128) wt_filter(const float* __restrict__ wavetable,
                                                 const float* __restrict__ h,
                                                 const float* __restrict__ lp2) {
    __shared__ float xs[898];     // [0,1]: zero history; samples at 2..897 (padded)
    __shared__ float ys[898];
    __shared__ float2 sv[128];
    __shared__ float Pw[7][4];    // A^(7*2^s)
    __shared__ float cf[10];
    int t = threadIdx.x;

    for (int p = t; p < 896; p += 128) xs[2 + p] = (p < W) ? wavetable[p] : 0.0f;
    if (t < 2) { xs[t] = 0.0f; ys[t] = 0.0f; }

    if (t == 0) {
        double h1 = h[1], h2 = h[2];
        double lpf = h1 * SRATE / 4.0; lpf = fmin(fmax(lpf, 100.0), SRATE / 2.0 - 1.0);
        double lpq = fmin(fmax(h2, 0.1), 0.999);
        double w0 = 2.0 * M_PI * lpf / SRATE, al = sin(w0) / (2.0 * lpq), cw = cos(w0);
        double a0 = 1.0 + al;
        cf[0] = (float)(((1.0 - cw) * 0.5) / a0);
        cf[1] = (float)((1.0 - cw) / a0);
        cf[2] = cf[0];
        cf[3] = (float)((-2.0 * cw) / a0);
        cf[4] = (float)((1.0 - al) / a0);

        double c2 = 100.0 + (double)lp2[0] * 8000.0;
        double w02 = 2.0 * M_PI * c2 / SRATE, al2 = sin(w02) / (2.0 * 0.707), cw2 = cos(w02);
        double a02 = 1.0 + al2;
        cf[5] = (float)(((1.0 - cw2) * 0.5) / a02);
        cf[6] = (float)((1.0 - cw2) / a02);
        cf[7] = cf[5];
        cf[8] = (float)((-2.0 * cw2) / a02);
        cf[9] = (float)((1.0 - al2) / a02);
    }
    __syncthreads();

    #pragma unroll
    for (int f = 0; f < 2; f++) {
        float b0 = cf[5 * f + 0], b1 = cf[5 * f + 1], b2 = cf[5 * f + 2];
        float a1 = cf[5 * f + 3], a2 = cf[5 * f + 4];
        const float* in = (f == 0) ? xs : ys;
        int base = 2 + 7 * t;

        // zero-init run
        float y1 = 0.f, y2 = 0.f;
        #pragma unroll
        for (int i = 0; i < 7; i++) {
            float cn = b0 * in[base + i] + b1 * in[base + i - 1] + b2 * in[base + i - 2];
            float yn = cn - a1 * y1 - a2 * y2;
            y2 = y1; y1 = yn;
        }
        sv[t] = make_float2(y1, y2);

        if (t == 0) {     // A^(7*2^s) in double
            double A00 = -(double)a1, A01 = -(double)a2, A10 = 1.0, A11 = 0.0;
            double p00 = A00, p01 = A01, p10 = A10, p11 = A11;   // A^1
            // A^7 = ((A^2)^2 * A^2) * A
            double q00, q01, q10, q11;
            q00 = p00*p00 + p01*p10; q01 = p00*p01 + p01*p11;    // A^2
            q10 = p10*p00 + p11*p10; q11 = p10*p01 + p11*p11;
            double r00, r01, r10, r11;
            r00 = q00*q00 + q01*q10; r01 = q00*q01 + q01*q11;    // A^4
            r10 = q10*q00 + q11*q10; r11 = q10*q01 + q11*q11;
            double s00, s01, s10, s11;
            s00 = r00*q00 + r01*q10; s01 = r00*q01 + r01*q11;    // A^6
            s10 = r10*q00 + r11*q10; s11 = r10*q01 + r11*q11;
            double m00, m01, m10, m11;
            m00 = s00*p00 + s01*p10; m01 = s00*p01 + s01*p11;    // A^7
            m10 = s10*p00 + s11*p10; m11 = s10*p01 + s11*p11;
            for (int s = 0; s < 7; s++) {
                Pw[s][0] = (float)m00; Pw[s][1] = (float)m01;
                Pw[s][2] = (float)m10; Pw[s][3] = (float)m11;
                double n00 = m00*m00 + m01*m10, n01 = m00*m01 + m01*m11;
                double n10 = m10*m00 + m11*m10, n11 = m10*m01 + m11*m11;
                m00 = n00; m01 = n01; m10 = n10; m11 = n11;
            }
        }
        __syncthreads();

        // Kogge-Stone scan over 128 affine states
        for (int s = 0; s < 7; s++) {
            int off = 1 << s;
            float ax = 0.f, ay = 0.f;
            if (t >= off) {
                float2 src = sv[t - off];
                ax = Pw[s][0] * src.x + Pw[s][1] * src.y;
                ay = Pw[s][2] * src.x + Pw[s][3] * src.y;
            }
            __syncthreads();
            sv[t].x += ax; sv[t].y += ay;
            __syncthreads();
        }

        // exclusive state, replay
        float py1 = 0.f, py2 = 0.f;
        if (t > 0) { py1 = sv[t - 1].x; py2 = sv[t - 1].y; }
        #pragma unroll
        for (int i = 0; i < 7; i++) {
            float cn = b0 * in[base + i] + b1 * in[base + i - 1] + b2 * in[base + i - 2];
            float yn = cn - a1 * py1 - a2 * py2;
            py2 = py1; py1 = yn;
            if (f == 0) ys[base + i] = yn;
            else { int g = 7 * t + i; if (g < W) g_wt[g] = yn; }
        }
        __syncthreads();
    }
}

// ============================================================
// Circular-conv helpers. f[t] = v[(t - AOFF) mod W]
// ============================================================
__device__ __forceinline__ void f_write(float* f, int p, float v) {
    f[p + AOFF] = v;
    if (p >= W - AOFF) f[p - (W - AOFF)] = v;
    if (p < FSZ - (W + AOFF)) f[p + W + AOFF] = v;
}

__device__ __forceinline__ void conv_into(const float* __restrict__ f,
                                          const float* __restrict__ Ks,
                                          int wk, int off, int o0, float* acc) {
    int b0 = o0 + off;
    float4 da = *(const float4*)&f[b0];
    #pragma unroll 2
    for (int jj = 0; jj < wk; jj += 4) {
        float4 ka = *(const float4*)&Ks[jj];
        float4 db = *(const float4*)&f[b0 + jj + 4];
        acc[0] = fmaf(ka.x, da.x, acc[0]); acc[0] = fmaf(ka.y, da.y, acc[0]);
        acc[0] = fmaf(ka.z, da.z, acc[0]); acc[0] = fmaf(ka.w, da.w, acc[0]);
        acc[1] = fmaf(ka.x, da.y, acc[1]); acc[1] = fmaf(ka.y, da.z, acc[1]);
        acc[1] = fmaf(ka.z, da.w, acc[1]); acc[1] = fmaf(ka.w, db.x, acc[1]);
        acc[2] = fmaf(ka.x, da.z, acc[2]); acc[2] = fmaf(ka.y, da.w, acc[2]);
        acc[2] = fmaf(ka.z, db.x, acc[2]); acc[2] = fmaf(ka.w, db.y, acc[2]);
        acc[3] = fmaf(ka.x, da.w, acc[3]); acc[3] = fmaf(ka.y, db.x, acc[3]);
        acc[3] = fmaf(ka.z, db.y, acc[3]); acc[3] = fmaf(ka.w, db.z, acc[3]);
        da = db;
    }
}

// ============================================================
// Karplus chunk runner: 1 barrier/step, prefetch depth 4
// ============================================================
template<int NS, bool WRITE>
__device__ __forceinline__ void ks_run(const float* __restrict__ fp,
                                       float* __restrict__ op,
                                       float& a, float (*b)[W],
                                       bool act, int i, int im1,
                                       float d2, float fa2) {
    float xr[4];
    #pragma unroll
    for (int q = 0; q < 4; q++)
        xr[q] = (act && q < NS) ? fp[(size_t)q * W] : 0.0f;

    #pragma unroll 4
    for (int s = 0; s < NS; s++) {
        float x = xr[s & 3];
        if (act && (s + 4) < NS) xr[s & 3] = fp[(size_t)(s + 4) * W];
        float u = ftanh2(fa2 * x);
        float t = a + u;
        if (act) b[s & 1][i] = t;
        __syncthreads();
        if (act) {
            a = d2 * (t + b[s & 1][im1]);
            if (WRITE) op[(size_t)s * W] = a;
        }
    }
}

// ============================================================
// Karplus pass 1
// ============================================================
__global__ void __launch_bounds__(896) ks_pass1(const float* __restrict__ fb) {
    __shared__ float b[2][W];
    int c = blockIdx.x;
    int i = threadIdx.x;
    bool act = i < W;
    int im1 = (i == 0) ? (W - 1) : (i - 1);
    float d2 = g_par[0], fa2 = g_par[1];

    float a = 0.0f;
    const float* fp = fb + (size_t)c * MCH * W + i;
    ks_run<MCH, false>(fp, nullptr, a, b, act, i, im1, d2, fa2);
    if (act) g_dstate[c * WP + i] = a;
}

// ============================================================
// Combine phase A: 8 groups parallel, dstate prefetched
// ============================================================
__global__ void __launch_bounds__(256) comb_A() {
    __shared__ __align__(16) float f[FSZ];
    __shared__ __align__(16) float Ks[256];
    int g = blockIdx.x, t = threadIdx.x;
    Ks[t] = g_Kt[t];                       // k=1 row
    int wk = g_Kwk[1], off = g_Koff[1];
    int c1 = g * GLEN;
    int len = (g == NG - 1) ? (NCH - (NG - 1) * GLEN) : GLEN;
    int cend  = c1 + len;
    int cendT = (g == NG - 1) ? (NCH - 1) : cend;

    int cbeg;
    if (g == 0) {
        for (int p = t; p < W; p += 256) {
            float v = g_wt[p];
            f_write(f, p, v);
            g_vstart[p] = v;
        }
        cbeg = 1;
    } else {
        for (int p = t; p < W; p += 256) {
            float v = g_dstate[c1 * WP + p];
            f_write(f, p, v);
            g_vstart[(c1 + 1) * WP + p] = v;
        }
        cbeg = c1 + 2;
    }
    __syncthreads();

    int o0 = t * 4;
    bool activ = o0 < W;
    float4 dv = make_float4(0.f, 0.f, 0.f, 0.f);
    if (activ) dv = *(const float4*)(g_dstate + (size_t)(cbeg - 1) * WP + o0);

    for (int c = cbeg; c <= cendT; c++) {
        float4 dnext = make_float4(0.f, 0.f, 0.f, 0.f);
        if (activ && c <= cendT - 1)
            dnext = *(const float4*)(g_dstate + (size_t)c * WP + o0);

        float acc[4] = {dv.x, dv.y, dv.z, dv.w};
        if (activ) conv_into(f, Ks, wk, off, o0, acc);
        __syncthreads();
        if (activ) {
            float* dst;
            if (c < cend) dst = g_vstart + (size_t)c * WP + o0;
            else if (g == 0) dst = g_gx + WP + o0;        // X_1
            else dst = g_gend + (size_t)g * WP + o0;      // Z_g
            #pragma unroll
            for (int e = 0; e < 4; e++) {
                int p = o0 + e;
                if (p < W) { f_write(f, p, acc[e]); dst[e] = acc[e]; }
            }
        }
        __syncthreads();
        dv = dnext;
    }
}

// ============================================================
// Combine phase B: X_{g+1} = K19 (*) X_g + Z_g, g=1..6
// ============================================================
__global__ void __launch_bounds__(256) comb_B() {
    __shared__ __align__(16) float f[FSZ];
    __shared__ __align__(16) float Ks[256];
    int t = threadIdx.x;
    Ks[t] = g_Kt[(GLEN - 1) * 256 + t];
    int wk = g_Kwk[GLEN], off = g_Koff[GLEN];

    for (int p = t; p < W; p += 256) f_write(f, p, g_gx[WP + p]);
    __syncthreads();

    int o0 = t * 4;
    bool activ = o0 < W;
    float4 zv = make_float4(0.f, 0.f, 0.f, 0.f);
    if (activ) zv = *(const float4*)(g_gend + WP + o0);

    for (int g = 1; g <= NG - 2; g++) {
        float4 znext = make_float4(0.f, 0.f, 0.f, 0.f);
        if (activ && g < NG - 2)
            znext = *(const float4*)(g_gend + (size_t)(g + 1) * WP + o0);
        float acc[4] = {zv.x, zv.y, zv.z, zv.w};
        if (activ) conv_into(f, Ks, wk, off, o0, acc);
        __syncthreads();
        if (activ) {
            float* dst = g_gx + (size_t)(g + 1) * WP + o0;
            #pragma unroll
            for (int e = 0; e < 4; e++) {
                int p = o0 + e;
                if (p < W) { f_write(f, p, acc[e]); dst[e] = acc[e]; }
            }
        }
        __syncthreads();
        zv = znext;
    }
}

// ============================================================
// Combine phase C: correct chunks 19..148 in parallel
// ============================================================
__global__ void __launch_bounds__(256) comb_C() {
    __shared__ __align__(16) float f[FSZ];
    __shared__ __align__(16) float Ks[256];
    int t = threadIdx.x;
    int c = GLEN + blockIdx.x;
    int g = c / GLEN, r = c - g * GLEN;

    if (r == 0) {
        for (int p = t; p < W; p += 256)
            g_vstart[(size_t)c * WP + p] = g_gx[(size_t)g * WP + p];
        return;
    }

    Ks[t] = g_Kt[(r - 1) * 256 + t];
    int wk = g_Kwk[r], off = g_Koff[r];
    for (int p = t; p < W; p += 256) f_write(f, p, g_gx[(size_t)g * WP + p]);
    __syncthreads();

    int o0 = t * 4;
    if (o0 < W) {
        float* vp = g_vstart + (size_t)c * WP + o0;
        float acc[4] = {vp[0], vp[1], vp[2], vp[3]};
        conv_into(f, Ks, wk, off, o0, acc);
        #pragma unroll
        for (int e = 0; e < 4; e++)
            if (o0 + e < W) vp[e] = acc[e];
    }
}

// ============================================================
// Karplus pass 2
// ============================================================
__global__ void __launch_bounds__(896) ks_pass2(const float* __restrict__ fb) {
    __shared__ float b[2][W];
    int c = blockIdx.x;
    int i = threadIdx.x;
    bool act = i < W;
    int im1 = (i == 0) ? (W - 1) : (i - 1);
    float d2 = g_par[0], fa2 = g_par[1];

    float a = act ? g_vstart[(size_t)c * WP + i] : 0.0f;
    __syncthreads();

    const float* fp = fb   + (size_t)c * MCH * W + i;
    float*       op = g_ks + (size_t)c * MCH * W + i;

    if (c < NCH - 1) {
        ks_run<MCH, true>(fp, op, a, b, act, i, im1, d2, fa2);
    } else {
        ks_run<LASTS, true>(fp, op, a, b, act, i, im1, d2, fa2);
        __syncthreads();
        if (act) b[0][i] = a;
        __syncthreads();
        if (i < REM) {
            float fin = d2 * (b[0][i] + b[0][im1]);
            int g = NB * W + i;
            if (g >= N_TOT - 256) fin *= (float)(N_TOT - 1 - g) * (1.0f / 255.0f);
            g_ks[g] = fin;
        }
    }
}

// ============================================================
// Band-reject pass A: zero-init chunk runs, ring-16 prefetch
// ============================================================
__global__ void __launch_bounds__(128) bq_passA() {
    int c = blockIdx.x * 128 + threadIdx.x;
    float b0 = g_par[2], b1 = g_par[3], b2 = g_par[4], a1 = g_par[5], a2 = g_par[6];
    size_t start = (size_t)c * LBQ;
    float x1 = (c > 0) ? g_ks[start - 1] : 0.0f;
    float x2 = (c > 0) ? g_ks[start - 2] : 0.0f;
    float y1 = 0.0f, y2 = 0.0f;
    const float4* kp = (const float4*)(g_ks + start);
    float4 buf[16];
    #pragma unroll
    for (int q = 0; q < 16; q++) buf[q] = kp[q];
    #pragma unroll 16
    for (int q = 0; q < LBQ / 4; q++) {
        float4 v = buf[q & 15];
        if (q + 16 < LBQ / 4) buf[q & 15] = kp[q + 16];
        float xs[4] = {v.x, v.y, v.z, v.w};
        #pragma unroll
        for (int e = 0; e < 4; e++) {
            float xn = xs[e];
            float cn = b0 * xn + b1 * x1 + b2 * x2;
            float yn = cn - a1 * y1 - a2 * y2;
            x2 = x1; x1 = xn; y2 = y1; y1 = yn;
        }
    }
    g_bqd[2 * c] = y1;
    g_bqd[2 * c + 1] = y2;
}

// ============================================================
// Band-reject scan: 512 threads x 32 chunks, Kogge-Stone 9 lvls
// ============================================================
__global__ void __launch_bounds__(512) bq_scan() {
    __shared__ float2 sv[512];
    int t = threadIdx.x;
    float A00 = (float)g_Ms[0][0], A01 = (float)g_Ms[0][1];
    float A10 = (float)g_Ms[0][2], A11 = (float)g_Ms[0][3];

    float4 db[CPT / 2];
    #pragma unroll
    for (int i = 0; i < CPT / 2; i++)
        db[i] = ((const float4*)g_bqd)[t * (CPT / 2) + i];

    float vx = 0.f, vy = 0.f;
    #pragma unroll
    for (int i = 0; i < CPT / 2; i++) {
        float nx = A00 * vx + A01 * vy + db[i].x;
        float ny = A10 * vx + A11 * vy + db[i].y;
        vx = nx; vy = ny;
        nx = A00 * vx + A01 * vy + db[i].z;
        ny = A10 * vx + A11 * vy + db[i].w;
        vx = nx; vy = ny;
    }
    sv[t] = make_float2(vx, vy);
    __syncthreads();

    for (int s = 0; s < 9; s++) {
        int offs = 1 << s;
        float B00 = (float)g_Ms[5 + s][0], B01 = (float)g_Ms[5 + s][1];
        float B10 = (float)g_Ms[5 + s][2], B11 = (float)g_Ms[5 + s][3];
        float ax = 0.f, ay = 0.f;
        if (t >= offs) {
            float2 src = sv[t - offs];
            ax = B00 * src.x + B01 * src.y;
            ay = B10 * src.x + B11 * src.y;
        }
        __syncthreads();
        sv[t].x += ax; sv[t].y += ay;
        __syncthreads();
    }

    float px = 0.f, py = 0.f;
    if (t > 0) { px = sv[t - 1].x; py = sv[t - 1].y; }
    #pragma unroll
    for (int i = 0; i < CPT / 2; i++) {
        float4 d = db[i];
        db[i].x = px; db[i].y = py;
        float nx = A00 * px + A01 * py + d.x;
        float ny = A10 * px + A11 * py + d.y;
        px = nx; py = ny;
        db[i].z = px; db[i].w = py;
        nx = A00 * px + A01 * py + d.z;
        ny = A10 * px + A11 * py + d.w;
        px = nx; py = ny;
    }
    #pragma unroll
    for (int i = 0; i < CPT / 2; i++)
        ((float4*)g_bqs)[t * (CPT / 2) + i] = db[i];
}

// ============================================================
// Band-reject pass B: replay + fused envelope
// ============================================================
__global__ void __launch_bounds__(128) bq_passB(float* __restrict__ out) {
    int c = blockIdx.x * 128 + threadIdx.x;
    float b0 = g_par[2], b1 = g_par[3], b2 = g_par[4], a1 = g_par[5], a2 = g_par[6];
    float ia = g_par[7], ir = g_par[8], sg = g_par[9];
    size_t start = (size_t)c * LBQ;
    float x1 = (c > 0) ? g_ks[start - 1] : 0.0f;
    float x2 = (c > 0) ? g_ks[start - 2] : 0.0f;
    float y1 = g_bqs[2 * c], y2 = g_bqs[2 * c + 1];
    const float4* kp = (const float4*)(g_ks + start);
    float4*       op = (float4*)(out + start);
    float4 buf[16];
    #pragma unroll
    for (int q = 0; q < 16; q++) buf[q] = kp[q];
    #pragma unroll 16
    for (int q = 0; q < LBQ / 4; q++) {
        float4 v = buf[q & 15];
        if (q + 16 < LBQ / 4) buf[q & 15] = kp[q + 16];
        float xs[4] = {v.x, v.y, v.z, v.w};
        float ys[4];
        int n0 = (int)start + q * 4;
        #pragma unroll
        for (int e = 0; e < 4; e++) {
            float xn = xs[e];
            float cn = b0 * xn + b1 * x1 + b2 * x2;
            float yn = cn - a1 * y1 - a2 * y2;
            x2 = x1; x1 = xn; y2 = y1; y1 = yn;
            float fn = (float)(n0 + e);
            float e1 = fminf(fn * ia, 1.0f);
            float e2 = fminf(((float)(N_TOT - 1) - fn) * ir, 1.0f);
            ys[e] = yn * e1 * e2 * sg;
        }
        op[q] = make_float4(ys[0], ys[1], ys[2], ys[3]);
    }
}

// ============================================================
extern "C" void kernel_launch(void* const* d_in, const int* in_sizes, int n_in,
                              void* d_out, int out_size) {
    const float* fb  = (const float*)d_in[0];
    const float* wt  = (const float*)d_in[1];
    const float* h   = (const float*)d_in[2];
    const float* ep  = (const float*)d_in[3];
    const float* lp2 = (const float*)d_in[4];
    float* out = (float*)d_out;

    setup_scalars<<<1, 32>>>(h, ep);
    ktab_kernel<<<152, 32>>>(h);
    wt_filter<<<1, 128>>>(wt, h, lp2);
    ks_pass1<<<NCH - 1, 896>>>(fb);
    comb_A<<<NG, 256>>>();
    comb_B<<<1, 256>>>();
    comb_C<<<NCH - GLEN, 256>>>();
    ks_pass2<<<NCH, 896>>>(fb);
    bq_passA<<<PBQ / 128, 128>>>();
    bq_scan<<<1, 512>>>();
    bq_passB<<<PBQ / 128, 128>>>(out);
}

// round 6
// speedup vs baseline: 2.3580x; 1.0552x over previous
#include <cuda_runtime.h>
#include <math.h>

#ifndef M_PI
#define M_PI 3.14159265358979323846
#endif

#define N_TOT   8388608
#define W       882
#define WP      884           // padded row stride
#define NB      9510
#define REM     788
#define MCH     64            // karplus steps per chunk
#define NCH     149           // total chunks (last has 38 steps)
#define LASTS   38
#define GLEN    19            // karplus chunks per group
#define NG      8             // groups
#define AOFF    768
#define FSZ     1660
#define LBQ     512
#define PBQ     16384
#define CPT     32
#define SRATE   44100.0

// ---- scratch ----
__device__ float  g_wt[W];
__device__ float  g_dstate[NCH * WP];
__device__ float  g_vstart[NCH * WP];
__device__ float  g_gend[NG * WP];
__device__ float  g_gx[NG * WP];
__device__ float  g_ks[N_TOT];
__device__ float  g_bqd[PBQ * 2];
__device__ float  g_bqs[PBQ * 2];
__device__ double g_Ms[16][4];
__device__ float  g_par[12];
__device__ float  g_Kt[GLEN * 256];
__device__ int    g_Kwk[GLEN + 1];
__device__ int    g_Koff[GLEN + 1];

__device__ __forceinline__ void kgeom(int k, int& c0, int& wk) {
    int m = 64 * k;
    int hw = (int)ceil(21.0 * sqrt((double)k));
    c0 = m / 2 - hw;
    wk = (2 * hw + 4) & ~3;
    c0 -= (c0 + wk - 1) & 3;      // force (c0+wk) % 4 == 1
}

__device__ __forceinline__ float ftanh2(float x2) {   // x2 = 2*x
    float e = __expf(x2);
    return __fdividef(e - 1.0f, e + 1.0f);
}

// ============================================================
// prep: block 0 = scalars/M-powers/LUT, block 1 = wavetable
// prefilter (blocked affine scan), blocks 2..39 = K-table.
// ============================================================
__global__ void __launch_bounds__(128) prep(const float* __restrict__ wavetable,
                                            const float* __restrict__ h,
                                            const float* __restrict__ envp,
                                            const float* __restrict__ lp2) {
    __shared__ float xs[898];
    __shared__ float ys[898];
    __shared__ float2 sv[128];
    __shared__ float Pw[7][4];
    __shared__ float cf[10];

    int b = blockIdx.x, t = threadIdx.x;

    if (b >= 2) {
        // ---- K table: reversed truncated taps of S^(64k) ----
        int idx = (b - 2) * 128 + t;      // 38*128 = 4864 = GLEN*256
        double decay = (double)h[0] / 10.0 + 0.9;
        decay = fmin(fmax(decay, 0.9), 0.999);
        double ld2 = log(decay * 0.5);
        int k = idx / 256 + 1;
        int jj = idx % 256;
        int c0, wk; kgeom(k, c0, wk);
        int m = 64 * k;
        float val = 0.0f;
        if (jj < wk) {
            int j = c0 + wk - 1 - jj;
            if (j >= 0 && j <= m) {
                double lg = lgamma((double)(m + 1)) - lgamma((double)(j + 1))
                          - lgamma((double)(m - j + 1)) + (double)m * ld2;
                val = (float)exp(lg);
            }
        }
        g_Kt[idx] = val;
        return;
    }

    if (b == 0) {
        // ---- scalars ----
        if (t >= 1 && t <= GLEN) {
            int c0, wk; kgeom(t, c0, wk);
            g_Kwk[t] = wk;
            g_Koff[t] = AOFF + 1 - c0 - wk;
        }
        if (t != 0) return;

        double decay = (double)h[0] / 10.0 + 0.9;
        decay = fmin(fmax(decay, 0.9), 0.999);

        double h5 = h[5], h6 = h[6];
        double brf = h5 * SRATE / 4.0; brf = fmin(fmax(brf, 100.0), SRATE / 2.0 - 1.0);
        double brq = fmin(fmax(h6, 0.1), 0.999);
        double w0b = 2.0 * M_PI * brf / SRATE, alb = sin(w0b) / (2.0 * brq), cwb = cos(w0b);
        double a0b = 1.0 + alb;
        double bb0 = 1.0 / a0b, bb1 = (-2.0 * cwb) / a0b, bb2 = 1.0 / a0b;
        double ba1 = (-2.0 * cwb) / a0b, ba2 = (1.0 - alb) / a0b;

        {
            double m00 = -ba1, m01 = -ba2, m10 = 1.0, m11 = 0.0;
            for (int s = 0; s < 9; s++) {                   // -> M^512
                double n00 = m00 * m00 + m01 * m10, n01 = m00 * m01 + m01 * m11;
                double n10 = m10 * m00 + m11 * m10, n11 = m10 * m01 + m11 * m11;
                m00 = n00; m01 = n01; m10 = n10; m11 = n11;
            }
            for (int s = 0; s < 16; s++) {
                g_Ms[s][0] = m00; g_Ms[s][1] = m01; g_Ms[s][2] = m10; g_Ms[s][3] = m11;
                double n00 = m00 * m00 + m01 * m10, n01 = m00 * m01 + m01 * m11;
                double n10 = m10 * m00 + m11 * m10, n11 = m10 * m01 + m11 * m11;
                m00 = n00; m01 = n01; m10 = n10; m11 = n11;
            }
        }

        double nD = (double)N_TOT;
        double attack  = 1.0 + (double)envp[0] * 0.1 * nD;
        double release = 1.0 + (double)envp[2] * 0.1 * nD;
        double sustain = fmin(fmax((double)envp[1], 0.0), 1.0);

        g_par[0] = (float)(decay * 0.5);
        g_par[1] = (float)(2.0 * (double)h[3]);
        g_par[2] = (float)bb0; g_par[3] = (float)bb1; g_par[4] = (float)bb2;
        g_par[5] = (float)ba1; g_par[6] = (float)ba2;
        g_par[7] = (float)(1.0 / attack);
        g_par[8] = (float)(1.0 / release);
        g_par[9] = (float)(sustain * (double)h[4]);
        return;
    }

    // ---- b == 1: wavetable prefilter (two biquads, blocked scan) ----
    for (int p = t; p < 896; p += 128) xs[2 + p] = (p < W) ? wavetable[p] : 0.0f;
    if (t < 2) { xs[t] = 0.0f; ys[t] = 0.0f; }

    if (t == 0) {
        double h1 = h[1], h2 = h[2];
        double lpf = h1 * SRATE / 4.0; lpf = fmin(fmax(lpf, 100.0), SRATE / 2.0 - 1.0);
        double lpq = fmin(fmax(h2, 0.1), 0.999);
        double w0 = 2.0 * M_PI * lpf / SRATE, al = sin(w0) / (2.0 * lpq), cw = cos(w0);
        double a0 = 1.0 + al;
        cf[0] = (float)(((1.0 - cw) * 0.5) / a0);
        cf[1] = (float)((1.0 - cw) / a0);
        cf[2] = cf[0];
        cf[3] = (float)((-2.0 * cw) / a0);
        cf[4] = (float)((1.0 - al) / a0);

        double c2 = 100.0 + (double)lp2[0] * 8000.0;
        double w02 = 2.0 * M_PI * c2 / SRATE, al2 = sin(w02) / (2.0 * 0.707), cw2 = cos(w02);
        double a02 = 1.0 + al2;
        cf[5] = (float)(((1.0 - cw2) * 0.5) / a02);
        cf[6] = (float)((1.0 - cw2) / a02);
        cf[7] = cf[5];
        cf[8] = (float)((-2.0 * cw2) / a02);
        cf[9] = (float)((1.0 - al2) / a02);
    }
    __syncthreads();

    #pragma unroll
    for (int f = 0; f < 2; f++) {
        float b0 = cf[5 * f + 0], b1 = cf[5 * f + 1], b2 = cf[5 * f + 2];
        float a1 = cf[5 * f + 3], a2 = cf[5 * f + 4];
        const float* in = (f == 0) ? xs : ys;
        int base = 2 + 7 * t;

        float y1 = 0.f, y2 = 0.f;
        #pragma unroll
        for (int i = 0; i < 7; i++) {
            float cn = b0 * in[base + i] + b1 * in[base + i - 1] + b2 * in[base + i - 2];
            float yn = cn - a1 * y1 - a2 * y2;
            y2 = y1; y1 = yn;
        }
        sv[t] = make_float2(y1, y2);

        if (t == 0) {
            double A00 = -(double)a1, A01 = -(double)a2, A10 = 1.0, A11 = 0.0;
            double q00 = A00*A00 + A01*A10, q01 = A00*A01 + A01*A11;    // A^2
            double q10 = A10*A00 + A11*A10, q11 = A10*A01 + A11*A11;
            double r00 = q00*q00 + q01*q10, r01 = q00*q01 + q01*q11;    // A^4
            double r10 = q10*q00 + q11*q10, r11 = q10*q01 + q11*q11;
            double s00 = r00*q00 + r01*q10, s01 = r00*q01 + r01*q11;    // A^6
            double s10 = r10*q00 + r11*q10, s11 = r10*q01 + r11*q11;
            double m00 = s00*A00 + s01*A10, m01 = s00*A01 + s01*A11;    // A^7
            double m10 = s10*A00 + s11*A10, m11 = s10*A01 + s11*A11;
            for (int s = 0; s < 7; s++) {
                Pw[s][0] = (float)m00; Pw[s][1] = (float)m01;
                Pw[s][2] = (float)m10; Pw[s][3] = (float)m11;
                double n00 = m00*m00 + m01*m10, n01 = m00*m01 + m01*m11;
                double n10 = m10*m00 + m11*m10, n11 = m10*m01 + m11*m11;
                m00 = n00; m01 = n01; m10 = n10; m11 = n11;
            }
        }
        __syncthreads();

        for (int s = 0; s < 7; s++) {
            int off = 1 << s;
            float ax = 0.f, ay = 0.f;
            if (t >= off) {
                float2 src = sv[t - off];
                ax = Pw[s][0] * src.x + Pw[s][1] * src.y;
                ay = Pw[s][2] * src.x + Pw[s][3] * src.y;
            }
            __syncthreads();
            sv[t].x += ax; sv[t].y += ay;
            __syncthreads();
        }

        float py1 = 0.f, py2 = 0.f;
        if (t > 0) { py1 = sv[t - 1].x; py2 = sv[t - 1].y; }
        #pragma unroll
        for (int i = 0; i < 7; i++) {
            float cn = b0 * in[base + i] + b1 * in[base + i - 1] + b2 * in[base + i - 2];
            float yn = cn - a1 * py1 - a2 * py2;
            py2 = py1; py1 = yn;
            if (f == 0) ys[base + i] = yn;
            else { int g = 7 * t + i; if (g < W) g_wt[g] = yn; }
        }
        __syncthreads();
    }
}

// ============================================================
// Circular-conv helpers
// ============================================================
__device__ __forceinline__ void f_write(float* f, int p, float v) {
    f[p + AOFF] = v;
    if (p >= W - AOFF) f[p - (W - AOFF)] = v;
    if (p < FSZ - (W + AOFF)) f[p + W + AOFF] = v;
}

__device__ __forceinline__ void conv_into(const float* __restrict__ f,
                                          const float* __restrict__ Ks,
                                          int wk, int off, int o0, float* acc) {
    int b0 = o0 + off;
    float4 da = *(const float4*)&f[b0];
    #pragma unroll 2
    for (int jj = 0; jj < wk; jj += 4) {
        float4 ka = *(const float4*)&Ks[jj];
        float4 db = *(const float4*)&f[b0 + jj + 4];
        acc[0] = fmaf(ka.x, da.x, acc[0]); acc[0] = fmaf(ka.y, da.y, acc[0]);
        acc[0] = fmaf(ka.z, da.z, acc[0]); acc[0] = fmaf(ka.w, da.w, acc[0]);
        acc[1] = fmaf(ka.x, da.y, acc[1]); acc[1] = fmaf(ka.y, da.z, acc[1]);
        acc[1] = fmaf(ka.z, da.w, acc[1]); acc[1] = fmaf(ka.w, db.x, acc[1]);
        acc[2] = fmaf(ka.x, da.z, acc[2]); acc[2] = fmaf(ka.y, da.w, acc[2]);
        acc[2] = fmaf(ka.z, db.x, acc[2]); acc[2] = fmaf(ka.w, db.y, acc[2]);
        acc[3] = fmaf(ka.x, da.w, acc[3]); acc[3] = fmaf(ka.y, db.x, acc[3]);
        acc[3] = fmaf(ka.z, db.y, acc[3]); acc[3] = fmaf(ka.w, db.z, acc[3]);
        da = db;
    }
}

// ============================================================
// Karplus runner: 2 steps per barrier round.
//  P1: compute u = tanh(fa*x) from xin(=fb), store u to uout.
//  !P1: xin is precomputed u; write outputs to op.
// ============================================================
template<int NR, bool P1>
__device__ __forceinline__ void ks_run2(const float* __restrict__ xin,
                                        float* __restrict__ uout,
                                        float* __restrict__ op,
                                        float& a,
                                        float (*bsh)[W], float (*ush)[W],
                                        bool act, int i, int im1, int im2,
                                        float d2, float fa2) {
    float xa[2], xb[2];
    #pragma unroll
    for (int q = 0; q < 2; q++) {
        xa[q] = act ? xin[(size_t)(2 * q) * W] : 0.f;
        xb[q] = act ? xin[(size_t)(2 * q + 1) * W] : 0.f;
    }
    #pragma unroll 2
    for (int r = 0; r < NR; r++) {
        float x0 = xa[r & 1], x1 = xb[r & 1];
        if (act && r + 2 < NR) {
            xa[r & 1] = xin[(size_t)(2 * r + 4) * W];
            xb[r & 1] = xin[(size_t)(2 * r + 5) * W];
        }
        float u0, u1;
        if (P1) {
            u0 = ftanh2(fa2 * x0);
            u1 = ftanh2(fa2 * x1);
            if (act) {
                uout[(size_t)(2 * r) * W] = u0;
                uout[(size_t)(2 * r + 1) * W] = u1;
            }
        } else { u0 = x0; u1 = x1; }

        float bb = a + u0;
        if (act) { bsh[r & 1][i] = bb; ush[r & 1][i] = u1; }
        __syncthreads();
        if (act) {
            float bm1 = bsh[r & 1][im1], bm2 = bsh[r & 1][im2];
            float u1m1 = ush[r & 1][im1];
            float a1  = d2 * (bb + bm1);
            float a1m = d2 * (bm1 + bm2);
            float a2  = d2 * ((a1 + u1) + (a1m + u1m1));
            if (!P1) {
                op[(size_t)(2 * r) * W] = a1;
                op[(size_t)(2 * r + 1) * W] = a2;
            }
            a = a2;
        }
    }
}

// ============================================================
// Karplus pass 1: zero-init ends + tanh precompute into uscr
// ============================================================
__global__ void __launch_bounds__(896) ks_pass1(const float* __restrict__ fb,
                                                float* __restrict__ uscr) {
    __shared__ float bsh[2][W];
    __shared__ float ush[2][W];
    int c = blockIdx.x, i = threadIdx.x;
    bool act = i < W;
    int im1 = (i == 0) ? (W - 1) : (i - 1);
    int im2 = (i <= 1) ? (i + W - 2) : (i - 2);
    float d2 = g_par[0], fa2 = g_par[1];

    float a = 0.0f;
    const float* fp = fb   + (size_t)c * MCH * W + i;
    float*       up = uscr + (size_t)c * MCH * W + i;
    if (c < NCH - 1) {
        ks_run2<MCH / 2, true>(fp, up, nullptr, a, bsh, ush, act, i, im1, im2, d2, fa2);
        if (act) g_dstate[c * WP + i] = a;
    } else {
        ks_run2<LASTS / 2, true>(fp, up, nullptr, a, bsh, ush, act, i, im1, im2, d2, fa2);
    }
}

// ============================================================
// Combine phase A
// ============================================================
__global__ void __launch_bounds__(256) comb_A() {
    __shared__ __align__(16) float f[FSZ];
    __shared__ __align__(16) float Ks[256];
    int g = blockIdx.x, t = threadIdx.x;
    Ks[t] = g_Kt[t];
    int wk = g_Kwk[1], off = g_Koff[1];
    int c1 = g * GLEN;
    int len = (g == NG - 1) ? (NCH - (NG - 1) * GLEN) : GLEN;
    int cend  = c1 + len;
    int cendT = (g == NG - 1) ? (NCH - 1) : cend;

    int cbeg;
    if (g == 0) {
        for (int p = t; p < W; p += 256) {
            float v = g_wt[p];
            f_write(f, p, v);
            g_vstart[p] = v;
        }
        cbeg = 1;
    } else {
        for (int p = t; p < W; p += 256) {
            float v = g_dstate[c1 * WP + p];
            f_write(f, p, v);
            g_vstart[(c1 + 1) * WP + p] = v;
        }
        cbeg = c1 + 2;
    }
    __syncthreads();

    int o0 = t * 4;
    bool activ = o0 < W;
    float4 dv = make_float4(0.f, 0.f, 0.f, 0.f);
    if (activ) dv = *(const float4*)(g_dstate + (size_t)(cbeg - 1) * WP + o0);

    for (int c = cbeg; c <= cendT; c++) {
        float4 dnext = make_float4(0.f, 0.f, 0.f, 0.f);
        if (activ && c <= cendT - 1)
            dnext = *(const float4*)(g_dstate + (size_t)c * WP + o0);

        float acc[4] = {dv.x, dv.y, dv.z, dv.w};
        if (activ) conv_into(f, Ks, wk, off, o0, acc);
        __syncthreads();
        if (activ) {
            float* dst;
            if (c < cend) dst = g_vstart + (size_t)c * WP + o0;
            else if (g == 0) dst = g_gx + WP + o0;        // X_1
            else dst = g_gend + (size_t)g * WP + o0;      // Z_g
            #pragma unroll
            for (int e = 0; e < 4; e++) {
                int p = o0 + e;
                if (p < W) { f_write(f, p, acc[e]); dst[e] = acc[e]; }
            }
        }
        __syncthreads();
        dv = dnext;
    }
}

// ============================================================
// Combine phase B
// ============================================================
__global__ void __launch_bounds__(256) comb_B() {
    __shared__ __align__(16) float f[FSZ];
    __shared__ __align__(16) float Ks[256];
    int t = threadIdx.x;
    Ks[t] = g_Kt[(GLEN - 1) * 256 + t];
    int wk = g_Kwk[GLEN], off = g_Koff[GLEN];

    for (int p = t; p < W; p += 256) f_write(f, p, g_gx[WP + p]);
    __syncthreads();

    int o0 = t * 4;
    bool activ = o0 < W;
    float4 zv = make_float4(0.f, 0.f, 0.f, 0.f);
    if (activ) zv = *(const float4*)(g_gend + WP + o0);

    for (int g = 1; g <= NG - 2; g++) {
        float4 znext = make_float4(0.f, 0.f, 0.f, 0.f);
        if (activ && g < NG - 2)
            znext = *(const float4*)(g_gend + (size_t)(g + 1) * WP + o0);
        float acc[4] = {zv.x, zv.y, zv.z, zv.w};
        if (activ) conv_into(f, Ks, wk, off, o0, acc);
        __syncthreads();
        if (activ) {
            float* dst = g_gx + (size_t)(g + 1) * WP + o0;
            #pragma unroll
            for (int e = 0; e < 4; e++) {
                int p = o0 + e;
                if (p < W) { f_write(f, p, acc[e]); dst[e] = acc[e]; }
            }
        }
        __syncthreads();
        zv = znext;
    }
}

// ============================================================
// Combine phase C
// ============================================================
__global__ void __launch_bounds__(256) comb_C() {
    __shared__ __align__(16) float f[FSZ];
    __shared__ __align__(16) float Ks[256];
    int t = threadIdx.x;
    int c = GLEN + blockIdx.x;
    int g = c / GLEN, r = c - g * GLEN;

    if (r == 0) {
        for (int p = t; p < W; p += 256)
            g_vstart[(size_t)c * WP + p] = g_gx[(size_t)g * WP + p];
        return;
    }

    Ks[t] = g_Kt[(r - 1) * 256 + t];
    int wk = g_Kwk[r], off = g_Koff[r];
    for (int p = t; p < W; p += 256) f_write(f, p, g_gx[(size_t)g * WP + p]);
    __syncthreads();

    int o0 = t * 4;
    if (o0 < W) {
        float* vp = g_vstart + (size_t)c * WP + o0;
        float acc[4] = {vp[0], vp[1], vp[2], vp[3]};
        conv_into(f, Ks, wk, off, o0, acc);
        #pragma unroll
        for (int e = 0; e < 4; e++)
            if (o0 + e < W) vp[e] = acc[e];
    }
}

// ============================================================
// Karplus pass 2: replay from exact starts using precomputed u
// ============================================================
__global__ void __launch_bounds__(896) ks_pass2(const float* __restrict__ uscr) {
    __shared__ float bsh[2][W];
    __shared__ float ush[2][W];
    int c = blockIdx.x, i = threadIdx.x;
    bool act = i < W;
    int im1 = (i == 0) ? (W - 1) : (i - 1);
    int im2 = (i <= 1) ? (i + W - 2) : (i - 2);
    float d2 = g_par[0];

    float a = act ? g_vstart[(size_t)c * WP + i] : 0.0f;
    __syncthreads();

    const float* up = uscr + (size_t)c * MCH * W + i;
    float*       op = g_ks + (size_t)c * MCH * W + i;

    if (c < NCH - 1) {
        ks_run2<MCH / 2, false>(up, nullptr, op, a, bsh, ush, act, i, im1, im2, d2, 0.f);
    } else {
        ks_run2<LASTS / 2, false>(up, nullptr, op, a, bsh, ush, act, i, im1, im2, d2, 0.f);
        __syncthreads();
        if (act) bsh[0][i] = a;
        __syncthreads();
        if (i < REM) {
            float fin = d2 * (bsh[0][i] + bsh[0][im1]);
            int g = NB * W + i;
            if (g >= N_TOT - 256) fin *= (float)(N_TOT - 1 - g) * (1.0f / 255.0f);
            g_ks[g] = fin;
        }
    }
}

// ============================================================
// Band-reject pass A
// ============================================================
__global__ void __launch_bounds__(128) bq_passA() {
    int c = blockIdx.x * 128 + threadIdx.x;
    float b0 = g_par[2], b1 = g_par[3], b2 = g_par[4], a1 = g_par[5], a2 = g_par[6];
    size_t start = (size_t)c * LBQ;
    float x1 = (c > 0) ? g_ks[start - 1] : 0.0f;
    float x2 = (c > 0) ? g_ks[start - 2] : 0.0f;
    float y1 = 0.0f, y2 = 0.0f;
    const float4* kp = (const float4*)(g_ks + start);
    float4 buf[16];
    #pragma unroll
    for (int q = 0; q < 16; q++) buf[q] = kp[q];
    #pragma unroll 16
    for (int q = 0; q < LBQ / 4; q++) {
        float4 v = buf[q & 15];
        if (q + 16 < LBQ / 4) buf[q & 15] = kp[q + 16];
        float xs[4] = {v.x, v.y, v.z, v.w};
        #pragma unroll
        for (int e = 0; e < 4; e++) {
            float xn = xs[e];
            float cn = b0 * xn + b1 * x1 + b2 * x2;
            float yn = cn - a1 * y1 - a2 * y2;
            x2 = x1; x1 = xn; y2 = y1; y1 = yn;
        }
    }
    g_bqd[2 * c] = y1;
    g_bqd[2 * c + 1] = y2;
}

// ============================================================
// Band-reject scan
// ============================================================
__global__ void __launch_bounds__(512) bq_scan() {
    __shared__ float2 sv[512];
    int t = threadIdx.x;
    float A00 = (float)g_Ms[0][0], A01 = (float)g_Ms[0][1];
    float A10 = (float)g_Ms[0][2], A11 = (float)g_Ms[0][3];

    float4 db[CPT / 2];
    #pragma unroll
    for (int i = 0; i < CPT / 2; i++)
        db[i] = ((const float4*)g_bqd)[t * (CPT / 2) + i];

    float vx = 0.f, vy = 0.f;
    #pragma unroll
    for (int i = 0; i < CPT / 2; i++) {
        float nx = A00 * vx + A01 * vy + db[i].x;
        float ny = A10 * vx + A11 * vy + db[i].y;
        vx = nx; vy = ny;
        nx = A00 * vx + A01 * vy + db[i].z;
        ny = A10 * vx + A11 * vy + db[i].w;
        vx = nx; vy = ny;
    }
    sv[t] = make_float2(vx, vy);
    __syncthreads();

    for (int s = 0; s < 9; s++) {
        int offs = 1 << s;
        float B00 = (float)g_Ms[5 + s][0], B01 = (float)g_Ms[5 + s][1];
        float B10 = (float)g_Ms[5 + s][2], B11 = (float)g_Ms[5 + s][3];
        float ax = 0.f, ay = 0.f;
        if (t >= offs) {
            float2 src = sv[t - offs];
            ax = B00 * src.x + B01 * src.y;
            ay = B10 * src.x + B11 * src.y;
        }
        __syncthreads();
        sv[t].x += ax; sv[t].y += ay;
        __syncthreads();
    }

    float px = 0.f, py = 0.f;
    if (t > 0) { px = sv[t - 1].x; py = sv[t - 1].y; }
    #pragma unroll
    for (int i = 0; i < CPT / 2; i++) {
        float4 d = db[i];
        db[i].x = px; db[i].y = py;
        float nx = A00 * px + A01 * py + d.x;
        float ny = A10 * px + A11 * py + d.y;
        px = nx; py = ny;
        db[i].z = px; db[i].w = py;
        nx = A00 * px + A01 * py + d.z;
        ny = A10 * px + A11 * py + d.w;
        px = nx; py = ny;
    }
    #pragma unroll
    for (int i = 0; i < CPT / 2; i++)
        ((float4*)g_bqs)[t * (CPT / 2) + i] = db[i];
}

// ============================================================
// Band-reject pass B: replay + fused envelope
// ============================================================
__global__ void __launch_bounds__(128) bq_passB(float* __restrict__ out) {
    int c = blockIdx.x * 128 + threadIdx.x;
    float b0 = g_par[2], b1 = g_par[3], b2 = g_par[4], a1 = g_par[5], a2 = g_par[6];
    float ia = g_par[7], ir = g_par[8], sg = g_par[9];
    size_t start = (size_t)c * LBQ;
    float x1 = (c > 0) ? g_ks[start - 1] : 0.0f;
    float x2 = (c > 0) ? g_ks[start - 2] : 0.0f;
    float y1 = g_bqs[2 * c], y2 = g_bqs[2 * c + 1];
    const float4* kp = (const float4*)(g_ks + start);
    float4*       op = (float4*)(out + start);
    float4 buf[16];
    #pragma unroll
    for (int q = 0; q < 16; q++) buf[q] = kp[q];
    #pragma unroll 16
    for (int q = 0; q < LBQ / 4; q++) {
        float4 v = buf[q & 15];
        if (q + 16 < LBQ / 4) buf[q & 15] = kp[q + 16];
        float xs[4] = {v.x, v.y, v.z, v.w};
        float ys[4];
        int n0 = (int)start + q * 4;
        #pragma unroll
        for (int e = 0; e < 4; e++) {
            float xn = xs[e];
            float cn = b0 * xn + b1 * x1 + b2 * x2;
            float yn = cn - a1 * y1 - a2 * y2;
            x2 = x1; x1 = xn; y2 = y1; y1 = yn;
            float fn = (float)(n0 + e);
            float e1 = fminf(fn * ia, 1.0f);
            float e2 = fminf(((float)(N_TOT - 1) - fn) * ir, 1.0f);
            ys[e] = yn * e1 * e2 * sg;
        }
        op[q] = make_float4(ys[0], ys[1], ys[2], ys[3]);
    }
}

// ============================================================
extern "C" void kernel_launch(void* const* d_in, const int* in_sizes, int n_in,
                              void* d_out, int out_size) {
    const float* fb  = (const float*)d_in[0];
    const float* wt  = (const float*)d_in[1];
    const float* h   = (const float*)d_in[2];
    const float* ep  = (const float*)d_in[3];
    const float* lp2 = (const float*)d_in[4];
    float* out = (float*)d_out;

    prep<<<40, 128>>>(wt, h, ep, lp2);
    ks_pass1<<<NCH, 896>>>(fb, out);       // also stores u -> out (scratch)
    comb_A<<<NG, 256>>>();
    comb_B<<<1, 256>>>();
    comb_C<<<NCH - GLEN, 256>>>();
    ks_pass2<<<NCH, 896>>>(out);           // reads u, writes g_ks
    bq_passA<<<PBQ / 128, 128>>>();
    bq_scan<<<1, 512>>>();
    bq_passB<<<PBQ / 128, 128>>>(out);
}